// round 16
// baseline (speedup 1.0000x reference)
#include <cuda_runtime.h>
#include <cstdint>

// ---------------------------------------------------------------------------
// SNN forward — fp32 bit-exact-chain, v8 "two-class queue".
//   Per-output fp32 FMA chain over ascending k (identical to R9-R13, R15).
//   All LIF/bias arithmetic contraction-proofed (__fmaf_rn/__fadd_rn/__fsub_rn).
//   One kernel per launch, CTAs split by blockIdx:
//     [0, SPLIT)   : warp-queue  — L1 32x32 tiles, sparse L2, lif0 chunks
//     [SPLIT, GRID): CTA-queue   — L0 64x128 CTA-cooperative tiles (1 B/FMA)
//   L0 slice t+5 scheduled in launch t; no serial L0 prologue.
// Output: [0, 25*256*1024) layer-2 spike record; then (256*1024) final mem2.
// ---------------------------------------------------------------------------

constexpr int T_STEPS = 25;
constexpr int BATCH   = 256;
constexpr int F0 = 1024, F1 = 2048, F2 = 2048, F3 = 1024;
constexpr int M0 = T_STEPS * BATCH;              // 6400

__device__ float g_wt0[F0 * F1];                 // W0^T [k][n]
__device__ float g_wt1[F1 * F2];                 // W1^T [k][n]
__device__ float g_wt2[F2 * F3];                 // W2^T [k][n]
__device__ float g_cur0T[F1 * M0];               // layer-0 currents [n][t*B+b]
__device__ float g_m0T[F1 * BATCH];              // layer-0 membranes [n][b]
__device__ float g_m1T[F2 * BATCH];              // layer-1 membranes [n][b]
__device__ float g_m2RM[BATCH * F3];             // layer-2 membranes row-major
__device__ float g_s0T[2][F1 * BATCH];           // layer-0 spikes k-major, dbl-buf
__device__ float g_s1RM[2][BATCH * F2];          // layer-1 spikes row-major, dbl-buf
__device__ unsigned int g_tick[64];              // per-launch {warp, cta} counters

// ----- fixed-rounding LIF (compilation-invariant) -------------------------------
__device__ __forceinline__ void lif_update(float mold, float cur,
                                           float& mnew, float& s) {
    float m = __fmaf_rn(0.9f, mold, cur);
    s = (m > 1.0f) ? 1.0f : 0.0f;
    mnew = __fsub_rn(m, s);
}

// ----- packed f32x2 helpers ------------------------------------------------------
__device__ __forceinline__ unsigned long long pk2(float x, float y) {
    unsigned long long r;
    asm("mov.b64 %0, {%1, %2};" : "=l"(r) : "f"(x), "f"(y));
    return r;
}
__device__ __forceinline__ void upk2(float& x, float& y, unsigned long long v) {
    asm("mov.b64 {%0, %1}, %2;" : "=f"(x), "=f"(y) : "l"(v));
}
#define FMA2(acc, a, b) \
    asm("fma.rn.f32x2 %0, %1, %2, %0;" : "+l"(acc) : "l"(a), "l"(b))
#define ADD2(acc, v) \
    asm("add.rn.f32x2 %0, %0, %1;" : "+l"(acc) : "l"(v))

#define CP_ASYNC16(dst, src) \
    asm volatile("cp.async.cg.shared.global [%0], [%1], 16;\n" :: "r"(dst), "l"(src))
#define CP_COMMIT() asm volatile("cp.async.commit_group;\n")
#define CP_WAIT1()  asm volatile("cp.async.wait_group 1;\n")
#define CP_WAIT0()  asm volatile("cp.async.wait_group 0;\n")

__device__ __forceinline__ uint32_t cvta_s(const void* p) {
    return (uint32_t)__cvta_generic_to_shared(p);
}

// ----- prep kernels ---------------------------------------------------------------
__global__ void zero_mems_kernel() {
    int idx = blockIdx.x * blockDim.x + threadIdx.x;
    int stride = gridDim.x * blockDim.x;
    for (int i = idx; i < BATCH * F2; i += stride) g_m1T[i] = 0.0f;
    for (int i = idx; i < BATCH * F3; i += stride) g_m2RM[i] = 0.0f;
    if (idx < 64) g_tick[idx] = 0u;
}

__global__ void transpose_kernel(const float* __restrict__ src,
                                 float* __restrict__ dst, int R, int C) {
    __shared__ float tile[32][33];
    int c0 = blockIdx.x * 32, r0 = blockIdx.y * 32;
    int tx = threadIdx.x, ty = threadIdx.y;          // 32 x 8
    #pragma unroll
    for (int j = 0; j < 32; j += 8)
        tile[ty + j][tx] = src[(size_t)(r0 + ty + j) * C + c0 + tx];
    __syncthreads();
    #pragma unroll
    for (int j = 0; j < 32; j += 8)
        dst[(size_t)(c0 + ty + j) * R + r0 + tx] = tile[tx][ty + j];
}

__global__ void copy_final_mem_kernel(float* __restrict__ dst) {
    int i = blockIdx.x * blockDim.x + threadIdx.x;
    if (i < BATCH * F3) dst[i] = g_m2RM[i];
}

// ---------------------------------------------------------------------------
// CTA-cooperative layer-0 tile: BM=64 x BN=128 x BK=32, micro 8x8, 128 thr.
// Ported verbatim from the passing R13 gemm_l0 (A read row-major from x).
// Writes cur0T[col][slice*256 + row] = __fadd_rn(acc, bias).
// ---------------------------------------------------------------------------
__device__ void cta_l0_tile(float* smem, int slice, int tile,
                            const float* __restrict__ x,
                            const float* __restrict__ WT,
                            const float* __restrict__ bias)
{
    constexpr int BK = 32, K = F0, N = F1;
    float (*As)[BK][68]  = reinterpret_cast<float(*)[BK][68]>(smem);
    float (*Bs)[BK][132] = reinterpret_cast<float(*)[BK][132]>(smem + 2 * BK * 68);

    const int tid = threadIdx.x;
    const int tx = tid & 15, ty = tid >> 4;
    const int bm_l = (tile >> 4) * 64;       // 4 m-tiles x 16 n-tiles
    const int bn   = (tile & 15) * 128;
    const int am = tid & 15, akc = tid >> 4;
    const int bnc = tid & 31, bkr = tid >> 5;
    const int mg0 = slice * BATCH + bm_l;    // global row base of this tile

    unsigned long long acc2[8][4];
    #pragma unroll
    for (int i = 0; i < 8; i++)
        #pragma unroll
        for (int p = 0; p < 4; p++) acc2[i][p] = 0ULL;

    const int ktiles = K / BK;
    float4 pa[4];

    #pragma unroll
    for (int i = 0; i < 8; i++)
        CP_ASYNC16(cvta_s(&Bs[0][bkr + 4 * i][bnc * 4]),
                   WT + (size_t)(bkr + 4 * i) * N + bn + bnc * 4);
    CP_COMMIT();
    #pragma unroll
    for (int i = 0; i < 4; i++)
        pa[i] = *reinterpret_cast<const float4*>(x + (size_t)(mg0 + am + 16 * i) * K + akc * 4);
    #pragma unroll
    for (int i = 0; i < 4; i++) {
        As[0][akc * 4 + 0][am + 16 * i] = pa[i].x;
        As[0][akc * 4 + 1][am + 16 * i] = pa[i].y;
        As[0][akc * 4 + 2][am + 16 * i] = pa[i].z;
        As[0][akc * 4 + 3][am + 16 * i] = pa[i].w;
    }
    CP_WAIT0();
    __syncthreads();

    for (int kt = 0; kt < ktiles; ++kt) {
        const int buf = kt & 1;
        if (kt + 1 < ktiles) {
            const int k0 = (kt + 1) * BK;
            #pragma unroll
            for (int i = 0; i < 8; i++)
                CP_ASYNC16(cvta_s(&Bs[buf ^ 1][bkr + 4 * i][bnc * 4]),
                           WT + (size_t)(k0 + bkr + 4 * i) * N + bn + bnc * 4);
            CP_COMMIT();
            #pragma unroll
            for (int i = 0; i < 4; i++)
                pa[i] = *reinterpret_cast<const float4*>(
                    x + (size_t)(mg0 + am + 16 * i) * K + k0 + akc * 4);
        }
        #pragma unroll
        for (int k = 0; k < BK; ++k) {
            float4 av0 = *reinterpret_cast<const float4*>(&As[buf][k][ty * 8]);
            float4 av1 = *reinterpret_cast<const float4*>(&As[buf][k][ty * 8 + 4]);
            float4 bv0 = *reinterpret_cast<const float4*>(&Bs[buf][k][tx * 8]);
            float4 bv1 = *reinterpret_cast<const float4*>(&Bs[buf][k][tx * 8 + 4]);
            unsigned long long bp[4] = {pk2(bv0.x, bv0.y), pk2(bv0.z, bv0.w),
                                        pk2(bv1.x, bv1.y), pk2(bv1.z, bv1.w)};
            const float a8[8] = {av0.x, av0.y, av0.z, av0.w, av1.x, av1.y, av1.z, av1.w};
            #pragma unroll
            for (int l = 0; l < 8; l++) {
                unsigned long long ad = pk2(a8[l], a8[l]);
                #pragma unroll
                for (int p = 0; p < 4; p++) FMA2(acc2[l][p], ad, bp[p]);
            }
        }
        if (kt + 1 < ktiles) {
            const int nb = buf ^ 1;
            #pragma unroll
            for (int i = 0; i < 4; i++) {
                As[nb][akc * 4 + 0][am + 16 * i] = pa[i].x;
                As[nb][akc * 4 + 1][am + 16 * i] = pa[i].y;
                As[nb][akc * 4 + 2][am + 16 * i] = pa[i].z;
                As[nb][akc * 4 + 3][am + 16 * i] = pa[i].w;
            }
        }
        CP_WAIT0();
        __syncthreads();
    }

    const int row0 = mg0 + ty * 8;           // global m row
    #pragma unroll
    for (int p = 0; p < 4; p++) {
        #pragma unroll
        for (int q = 0; q < 2; q++) {
            const int col = bn + tx * 8 + p * 2 + q;
            const float bcol = __ldg(&bias[col]);
            float v[8];
            #pragma unroll
            for (int i = 0; i < 8; i++) {
                float c0, c1;
                upk2(c0, c1, acc2[i][p]);
                v[i] = __fadd_rn(q ? c1 : c0, bcol);
            }
            float* cp = g_cur0T + (size_t)col * M0 + row0;
            *reinterpret_cast<float4*>(cp)     = make_float4(v[0], v[1], v[2], v[3]);
            *reinterpret_cast<float4*>(cp + 4) = make_float4(v[4], v[5], v[6], v[7]);
        }
    }
    __syncthreads();                         // protect smem before next ticket
}

// ---------------------------------------------------------------------------
// Warp-level layer-1 tile: 32x32, K=2048, BK=16 cp.async dblbuf (R15 verbatim).
// ---------------------------------------------------------------------------
__device__ __forceinline__ void warp_gemm_l1(
    float* wsm, uint32_t wsm_u,
    const float* __restrict__ A,             // s0T [2048][256]
    const float* __restrict__ W,             // wt1 [2048][2048]
    const float* __restrict__ bias,
    float* __restrict__ memT, float* __restrict__ s1rm,
    int bm, int bn, int lane)
{
    constexpr int KT = F1 / 16, N = F2;
    unsigned long long acc2[8][2];
    #pragma unroll
    for (int i = 0; i < 8; i++) { acc2[i][0] = 0ULL; acc2[i][1] = 0ULL; }

    const int ty = lane >> 3, tx = lane & 7;

    auto issue = [&](int st, int k0) {
        #pragma unroll
        for (int j = 0; j < 4; j++) {
            int c = lane + 32 * j;
            int kr = c >> 3, of = c & 7;
            CP_ASYNC16(wsm_u + (uint32_t)(st * 512 + kr * 32 + of * 4) * 4u,
                       A + (size_t)(k0 + kr) * BATCH + bm + of * 4);
        }
        #pragma unroll
        for (int j = 0; j < 4; j++) {
            int c = lane + 32 * j;
            int kr = c >> 3, of = c & 7;
            CP_ASYNC16(wsm_u + (uint32_t)(1024 + st * 512 + kr * 32 + of * 4) * 4u,
                       W + (size_t)(k0 + kr) * N + bn + of * 4);
        }
        CP_COMMIT();
    };

    issue(0, 0);
    for (int kt = 0; kt < KT; ++kt) {
        if (kt + 1 < KT) { issue((kt + 1) & 1, (kt + 1) * 16); CP_WAIT1(); }
        else             { CP_WAIT0(); }
        __syncwarp();
        const float* sA = wsm + (kt & 1) * 512;
        const float* sB = wsm + 1024 + (kt & 1) * 512;
        #pragma unroll
        for (int k = 0; k < 16; ++k) {
            float4 a0 = *reinterpret_cast<const float4*>(sA + k * 32 + ty * 8);
            float4 a1 = *reinterpret_cast<const float4*>(sA + k * 32 + ty * 8 + 4);
            float4 bv = *reinterpret_cast<const float4*>(sB + k * 32 + tx * 4);
            unsigned long long bp0 = pk2(bv.x, bv.y), bp1 = pk2(bv.z, bv.w);
            const float a8[8] = {a0.x, a0.y, a0.z, a0.w, a1.x, a1.y, a1.z, a1.w};
            #pragma unroll
            for (int l = 0; l < 8; l++) {
                unsigned long long ad = pk2(a8[l], a8[l]);
                FMA2(acc2[l][0], ad, bp0);
                FMA2(acc2[l][1], ad, bp1);
            }
        }
        __syncwarp();
    }

    const int row0 = bm + ty * 8;
    float sreg[8][4];
    #pragma unroll
    for (int p = 0; p < 2; p++) {
        #pragma unroll
        for (int q = 0; q < 2; q++) {
            const int col = bn + tx * 4 + p * 2 + q;
            const float bcol = __ldg(&bias[col]);
            float v[8];
            #pragma unroll
            for (int i = 0; i < 8; i++) {
                float c0, c1;
                upk2(c0, c1, acc2[i][p]);
                v[i] = __fadd_rn(q ? c1 : c0, bcol);
            }
            float* mp = memT + (size_t)col * BATCH + row0;
            float4 mlo = *reinterpret_cast<float4*>(mp);
            float4 mhi = *reinterpret_cast<float4*>(mp + 4);
            float mm[8] = {mlo.x, mlo.y, mlo.z, mlo.w, mhi.x, mhi.y, mhi.z, mhi.w};
            float ss[8];
            #pragma unroll
            for (int i = 0; i < 8; i++)
                lif_update(mm[i], v[i], mm[i], ss[i]);
            *reinterpret_cast<float4*>(mp)     = make_float4(mm[0], mm[1], mm[2], mm[3]);
            *reinterpret_cast<float4*>(mp + 4) = make_float4(mm[4], mm[5], mm[6], mm[7]);
            #pragma unroll
            for (int i = 0; i < 8; i++) sreg[i][p * 2 + q] = ss[i];
        }
    }
    #pragma unroll
    for (int i = 0; i < 8; i++) {
        const int row = row0 + i;
        *reinterpret_cast<float4*>(s1rm + (size_t)row * N + bn + tx * 4) =
            make_float4(sreg[i][0], sreg[i][1], sreg[i][2], sreg[i][3]);
    }
}

// ---------------------------------------------------------------------------
// SPARSE layer-2 task (R15 verbatim; skip-zero ADD2 == dense chain exactly).
// ---------------------------------------------------------------------------
__device__ __forceinline__ void sparse_l2(
    const float* __restrict__ s1b,
    const float* __restrict__ W2T,
    const float* __restrict__ bias,
    float* __restrict__ m2b,
    float* __restrict__ outb,
    int n0, int lane)
{
    unsigned long long acc[4][2];
    #pragma unroll
    for (int c = 0; c < 4; c++) { acc[c][0] = 0ULL; acc[c][1] = 0ULL; }

    for (int base = 0; base < F2; base += 128) {
        const float4 sv = *reinterpret_cast<const float4*>(s1b + base + lane * 4);
        unsigned bl0 = __ballot_sync(0xffffffffu, sv.x != 0.0f);
        unsigned bl1 = __ballot_sync(0xffffffffu, sv.y != 0.0f);
        unsigned bl2 = __ballot_sync(0xffffffffu, sv.z != 0.0f);
        unsigned bl3 = __ballot_sync(0xffffffffu, sv.w != 0.0f);
        unsigned any = bl0 | bl1 | bl2 | bl3;
        while (any) {
            const int L = __ffs(any) - 1;
            any &= any - 1;
            const int kb = base + L * 4;
            #pragma unroll
            for (int j = 0; j < 4; j++) {
                const unsigned blj = (j == 0) ? bl0 : (j == 1) ? bl1 : (j == 2) ? bl2 : bl3;
                if ((blj >> L) & 1u) {
                    const float* wr = W2T + (size_t)(kb + j) * F3 + n0;
                    #pragma unroll
                    for (int c = 0; c < 4; c++) {
                        float4 w = *reinterpret_cast<const float4*>(wr + c * 128 + lane * 4);
                        ADD2(acc[c][0], pk2(w.x, w.y));
                        ADD2(acc[c][1], pk2(w.z, w.w));
                    }
                }
            }
        }
    }

    #pragma unroll
    for (int c = 0; c < 4; c++) {
        const int n = n0 + c * 128 + lane * 4;
        float a0, a1, a2, a3;
        upk2(a0, a1, acc[c][0]);
        upk2(a2, a3, acc[c][1]);
        float4 bv = *reinterpret_cast<const float4*>(bias + n);
        float4 mv = *reinterpret_cast<const float4*>(m2b + n);
        float m0, m1, m2, m3, s0, s1, s2, s3;
        lif_update(mv.x, __fadd_rn(a0, bv.x), m0, s0);
        lif_update(mv.y, __fadd_rn(a1, bv.y), m1, s1);
        lif_update(mv.z, __fadd_rn(a2, bv.z), m2, s2);
        lif_update(mv.w, __fadd_rn(a3, bv.w), m3, s3);
        *reinterpret_cast<float4*>(m2b + n)  = make_float4(m0, m1, m2, m3);
        *reinterpret_cast<float4*>(outb + n) = make_float4(s0, s1, s2, s3);
    }
}

// ---------------------------------------------------------------------------
// Step kernel, two queues:
//   blockIdx <  warp_ctas : warp tickets (g_tick[2li])   — L1 / sparse / lif0
//   blockIdx >= warp_ctas : CTA tickets  (g_tick[2li+1]) — L0 64x128 tiles
// ---------------------------------------------------------------------------
__global__ __launch_bounds__(128)
void step_kernel(int li, int warp_ctas,
                 int nL1, int l1_par,
                 int nSP, int sp_par,
                 int nLIF, int lif_t,
                 int nL0, int l0_first,
                 const float* __restrict__ x,
                 const float* __restrict__ b0,
                 const float* __restrict__ b1,
                 const float* __restrict__ b2,
                 float* __restrict__ out_t)
{
    extern __shared__ float smem[];

    if ((int)blockIdx.x >= warp_ctas) {
        // ---- CTA-queue: layer-0 tiles ----
        __shared__ unsigned int s_tk;
        for (;;) {
            if (threadIdx.x == 0) s_tk = atomicAdd(&g_tick[2 * li + 1], 1u);
            __syncthreads();
            const unsigned tk = s_tk;
            __syncthreads();
            if (tk >= (unsigned)nL0) break;
            cta_l0_tile(smem, l0_first + (int)(tk >> 6), (int)(tk & 63),
                        x, g_wt0, b0);
        }
        return;
    }

    // ---- warp-queue ----
    const int warp = threadIdx.x >> 5, lane = threadIdx.x & 31;
    float* wsm = smem + warp * 2048;
    const uint32_t wsm_u = cvta_s(wsm);

    const int total = nL1 + nSP + nLIF;
    const float* l1A = g_s0T[l1_par];
    float* l1spk = g_s1RM[l1_par];
    const float* spS = g_s1RM[sp_par];

    for (;;) {
        unsigned int tk;
        if (lane == 0) tk = atomicAdd(&g_tick[2 * li], 1u);
        tk = __shfl_sync(0xffffffffu, tk, 0);
        if (tk >= (unsigned)total) break;

        if ((int)tk < nL1) {
            const int bm = (tk >> 6) * 32, bn = (int)(tk & 63) * 32;
            warp_gemm_l1(wsm, wsm_u, l1A, g_wt1, b1, g_m1T, l1spk, bm, bn, lane);
        } else if ((int)tk < nL1 + nSP) {
            const int j = tk - nL1;
            const int b = j >> 1, n0 = (j & 1) * 512;
            sparse_l2(spS + (size_t)b * F2, g_wt2, b2,
                      g_m2RM + (size_t)b * F3, out_t + (size_t)b * F3, n0, lane);
        } else {
            const int c = tk - nL1 - nSP;
            const float4* c4 = reinterpret_cast<const float4*>(g_cur0T);
            float4* m4 = reinterpret_cast<float4*>(g_m0T);
            float4* s4 = reinterpret_cast<float4*>(g_s0T[lif_t & 1]);
            const int toff4 = lif_t * (BATCH / 4);
            #pragma unroll 4
            for (int j = 0; j < 128; j++) {
                int f4 = c * 4096 + j * 32 + lane;
                int n = f4 >> 6, b4 = f4 & 63;
                float4 cur = c4[(size_t)n * (M0 / 4) + toff4 + b4];
                float4 m = (lif_t == 0) ? make_float4(0.f, 0.f, 0.f, 0.f) : m4[f4];
                float4 s;
                lif_update(m.x, cur.x, m.x, s.x);
                lif_update(m.y, cur.y, m.y, s.y);
                lif_update(m.z, cur.z, m.z, s.z);
                lif_update(m.w, cur.w, m.w, s.w);
                m4[f4] = m;
                s4[f4] = s;
            }
        }
    }
}

// ---------------------------------------------------------------------------
extern "C" void kernel_launch(void* const* d_in, const int* in_sizes, int n_in,
                              void* d_out, int out_size)
{
    (void)in_sizes; (void)n_in;
    const float* x  = (const float*)d_in[0];
    const float* w0 = (const float*)d_in[1];
    const float* b0 = (const float*)d_in[2];
    const float* w1 = (const float*)d_in[3];
    const float* b1 = (const float*)d_in[4];
    const float* w2 = (const float*)d_in[5];
    const float* b2 = (const float*)d_in[6];
    float* out = (float*)d_out;

    float *wt0, *wt1, *wt2;
    cudaGetSymbolAddress((void**)&wt0, g_wt0);
    cudaGetSymbolAddress((void**)&wt1, g_wt1);
    cudaGetSymbolAddress((void**)&wt2, g_wt2);

    // prep: weight transposes + zeroing (membranes, ticket counters)
    {
        dim3 blk(32, 8);
        transpose_kernel<<<dim3(F0 / 32, F1 / 32), blk>>>(w0, wt0, F1, F0);
        transpose_kernel<<<dim3(F1 / 32, F2 / 32), blk>>>(w1, wt1, F2, F1);
        transpose_kernel<<<dim3(F2 / 32, F3 / 32), blk>>>(w2, wt2, F3, F2);
        zero_mems_kernel<<<512, 256>>>();
    }

    // dynamic smem: max(L0 CTA path 51200 B, warp path 32768 B)
    const int SMEM = 2 * 32 * 68 * 4 + 2 * 32 * 132 * 4;   // 51200
    static bool attr_set = false;
    if (!attr_set) {
        cudaFuncSetAttribute(step_kernel,
                             cudaFuncAttributeMaxDynamicSharedMemorySize, SMEM);
        attr_set = true;
    }

    const int GRID = 444, SPLIT = 344;   // 344 warp-CTAs, 100 L0-CTAs
    int li = 0;

    // P0: all CTAs on L0 queue — slices 0,1,2 (192 tiles)
    step_kernel<<<GRID, 128, SMEM>>>(li++, 0, 0, 0, 0, 0, 0, 0, 192, 0,
                                     x, b0, b1, b2, nullptr);
    // P1: lif0(0) + L0 slice 3
    step_kernel<<<GRID, 128, SMEM>>>(li++, SPLIT, 0, 0, 0, 0, 32, 0, 64, 3,
                                     x, b0, b1, b2, nullptr);
    // P2: L1(0) + lif0(1) + L0 slice 4
    step_kernel<<<GRID, 128, SMEM>>>(li++, SPLIT, 512, 0, 0, 0, 32, 1, 64, 4,
                                     x, b0, b1, b2, nullptr);

    // main: per step t -> L2(t) + L1(t+1) + lif0(t+2) + L0 slice(t+5)
    for (int t = 0; t < T_STEPS - 1; ++t) {
        const int nLIF = (t + 2 <= T_STEPS - 1) ? 32 : 0;
        const int nL0  = (t + 5 <= T_STEPS - 1) ? 64 : 0;
        step_kernel<<<GRID, 128, SMEM>>>(li++, SPLIT,
                                         512, (t + 1) & 1,
                                         512, t & 1,
                                         nLIF, t + 2,
                                         nL0, t + 5,
                                         x, b0, b1, b2,
                                         out + (size_t)t * BATCH * F3);
    }
    // final: L2(24) only (all CTAs on warp queue)
    step_kernel<<<GRID, 128, SMEM>>>(li++, GRID, 0, 0, 512, (T_STEPS - 1) & 1,
                                     0, 0, 0, 0,
                                     x, b0, b1, b2,
                                     out + (size_t)(T_STEPS - 1) * BATCH * F3);

    const long long mem_off = (long long)T_STEPS * BATCH * F3;
    if ((long long)out_size >= mem_off + (long long)BATCH * F3) {
        copy_final_mem_kernel<<<(BATCH * F3 + 255) / 256, 256>>>(out + mem_off);
    }
}

// round 17
// speedup vs baseline: 4.2641x; 4.2641x over previous
#include <cuda_runtime.h>
#include <cstdint>

// ---------------------------------------------------------------------------
// SNN forward — fp32 bit-exact-chain, v9 "layer-unrolled".
//   The network is feed-forward in time (spikes feed forward; only the
//   elementwise membrane is recurrent), so each layer is ONE big GEMM over
//   M = 25*256 = 6400 rows, followed by a cheap elementwise LIF scan over t.
//   All arithmetic chains identical to passing R13:
//     GEMM: single fp32 fma.rn.f32x2 chain, k ascending
//     LIF:  __fmaf_rn(0.9,m,cur); s=(m>1); __fsub_rn(m,s)
//     L2:   sparse skip-zero add.rn.f32x2 over ascending k (spikes are 0/1)
// Output: [0, 25*256*1024) layer-2 spike record; then (256*1024) final mem2.
// ---------------------------------------------------------------------------

constexpr int T_STEPS = 25;
constexpr int BATCH   = 256;
constexpr int F0 = 1024, F1 = 2048, F2 = 2048, F3 = 1024;
constexpr int M0 = T_STEPS * BATCH;              // 6400

__device__ float g_wt0[F0 * F1];                 // W0^T [k][n]
__device__ float g_wt1[F1 * F2];                 // W1^T [k][n]
__device__ float g_wt2[F2 * F3];                 // W2^T [k][n]
__device__ float g_xT[F0 * M0];                  // x^T   [k][m]   m = t*256+b
__device__ float g_cur0T[F1 * M0];               // layer-0 currents [n][m]
__device__ float g_s0T[F1 * M0];                 // layer-0 spikes   [n][m]
__device__ float g_cur1T[F2 * M0];               // layer-1 currents [n][m]
__device__ float g_s1RM[M0 * F2];                // layer-1 spikes   [m][k] row-major
__device__ float g_cur2RM[M0 * F3];              // layer-2 currents [m][n] row-major

// ----- fixed-rounding LIF (compilation-invariant) -------------------------------
__device__ __forceinline__ void lif_update(float mold, float cur,
                                           float& mnew, float& s) {
    float m = __fmaf_rn(0.9f, mold, cur);
    s = (m > 1.0f) ? 1.0f : 0.0f;
    mnew = __fsub_rn(m, s);
}

// ----- packed f32x2 helpers ------------------------------------------------------
__device__ __forceinline__ unsigned long long pk2(float x, float y) {
    unsigned long long r;
    asm("mov.b64 %0, {%1, %2};" : "=l"(r) : "f"(x), "f"(y));
    return r;
}
__device__ __forceinline__ void upk2(float& x, float& y, unsigned long long v) {
    asm("mov.b64 {%0, %1}, %2;" : "=f"(x), "=f"(y) : "l"(v));
}
#define FMA2(acc, a, b) \
    asm("fma.rn.f32x2 %0, %1, %2, %0;" : "+l"(acc) : "l"(a), "l"(b))
#define ADD2(acc, v) \
    asm("add.rn.f32x2 %0, %0, %1;" : "+l"(acc) : "l"(v))

#define CP_ASYNC16(dst, src) \
    asm volatile("cp.async.cg.shared.global [%0], [%1], 16;\n" :: "r"(dst), "l"(src))
#define CP_COMMIT() asm volatile("cp.async.commit_group;\n")
#define CP_WAIT0()  asm volatile("cp.async.wait_group 0;\n")

__device__ __forceinline__ uint32_t cvta_s(const void* p) {
    return (uint32_t)__cvta_generic_to_shared(p);
}

// ----- transpose (prep) -----------------------------------------------------------
__global__ void transpose_kernel(const float* __restrict__ src,
                                 float* __restrict__ dst, int R, int C) {
    __shared__ float tile[32][33];
    int c0 = blockIdx.x * 32, r0 = blockIdx.y * 32;
    int tx = threadIdx.x, ty = threadIdx.y;          // 32 x 8
    #pragma unroll
    for (int j = 0; j < 32; j += 8)
        tile[ty + j][tx] = src[(size_t)(r0 + ty + j) * C + c0 + tx];
    __syncthreads();
    #pragma unroll
    for (int j = 0; j < 32; j += 8)
        dst[(size_t)(c0 + ty + j) * R + r0 + tx] = tile[tx][ty + j];
}

// ---------------------------------------------------------------------------
// Big GEMM: outT[n][m] = fadd( sum_k A[k][m]*WT[k][n], bias[n] )
//   A k-major [K][M0]; CTA tile 64(m) x 128(n) x BK=32, micro 8x8, 128 thr.
//   Both operands via cp.async (A is k-major -> no transpose STS).
//   Per-output chain: fma.rn.f32x2 ascending k — identical to R13.
// ---------------------------------------------------------------------------
__global__ __launch_bounds__(128)
void gemm_big(const float* __restrict__ A,
              const float* __restrict__ WT,
              const float* __restrict__ bias,
              float* __restrict__ outT,
              int K, int N)
{
    constexpr int BM = 64, BN = 128, BK = 32;
    __shared__ float As[2][BK][BM + 4];
    __shared__ float Bs[2][BK][BN + 4];

    const int tid = threadIdx.x;
    const int tx = tid & 15, ty = tid >> 4;
    const int bn = blockIdx.x * BN;
    const int bm = blockIdx.y * BM;

    // A loader: 32 k-rows x 16 chunks (16B) = 512 chunks, 4/thread
    const int a_row = tid >> 2, a_ch = tid & 3;      // +8*i rows? no: c=tid+128i
    // B loader: 32 k-rows x 32 chunks = 1024 chunks, 8/thread
    (void)a_row; (void)a_ch;

    unsigned long long acc2[8][4];
    #pragma unroll
    for (int i = 0; i < 8; i++)
        #pragma unroll
        for (int p = 0; p < 4; p++) acc2[i][p] = 0ULL;

    const int ktiles = K / BK;

    auto issue = [&](int st, int k0) {
        #pragma unroll
        for (int i = 0; i < 4; i++) {                // A chunks
            int c = tid + 128 * i;
            int kr = c >> 4, ch = c & 15;
            CP_ASYNC16(cvta_s(&As[st][kr][ch * 4]),
                       A + (size_t)(k0 + kr) * M0 + bm + ch * 4);
        }
        #pragma unroll
        for (int i = 0; i < 8; i++) {                // B chunks
            int c = tid + 128 * i;
            int kr = c >> 5, ch = c & 31;
            CP_ASYNC16(cvta_s(&Bs[st][kr][ch * 4]),
                       WT + (size_t)(k0 + kr) * N + bn + ch * 4);
        }
        CP_COMMIT();
    };

    issue(0, 0);
    CP_WAIT0();
    __syncthreads();

    for (int kt = 0; kt < ktiles; ++kt) {
        const int buf = kt & 1;
        if (kt + 1 < ktiles) issue(buf ^ 1, (kt + 1) * BK);

        #pragma unroll
        for (int k = 0; k < BK; ++k) {
            float4 av0 = *reinterpret_cast<const float4*>(&As[buf][k][ty * 8]);
            float4 av1 = *reinterpret_cast<const float4*>(&As[buf][k][ty * 8 + 4]);
            float4 bv0 = *reinterpret_cast<const float4*>(&Bs[buf][k][tx * 8]);
            float4 bv1 = *reinterpret_cast<const float4*>(&Bs[buf][k][tx * 8 + 4]);
            unsigned long long bp[4] = {pk2(bv0.x, bv0.y), pk2(bv0.z, bv0.w),
                                        pk2(bv1.x, bv1.y), pk2(bv1.z, bv1.w)};
            const float a8[8] = {av0.x, av0.y, av0.z, av0.w,
                                 av1.x, av1.y, av1.z, av1.w};
            #pragma unroll
            for (int l = 0; l < 8; l++) {
                unsigned long long ad = pk2(a8[l], a8[l]);
                #pragma unroll
                for (int p = 0; p < 4; p++) FMA2(acc2[l][p], ad, bp[p]);
            }
        }
        CP_WAIT0();
        __syncthreads();
    }

    // epilogue: outT[col][m] = __fadd_rn(acc, bias[col])   (R13 pattern)
    const int row0 = bm + ty * 8;
    #pragma unroll
    for (int p = 0; p < 4; p++) {
        #pragma unroll
        for (int q = 0; q < 2; q++) {
            const int col = bn + tx * 8 + p * 2 + q;
            const float bcol = __ldg(&bias[col]);
            float v[8];
            #pragma unroll
            for (int i = 0; i < 8; i++) {
                float c0, c1;
                upk2(c0, c1, acc2[i][p]);
                v[i] = __fadd_rn(q ? c1 : c0, bcol);
            }
            float* cp = outT + (size_t)col * M0 + row0;
            *reinterpret_cast<float4*>(cp)     = make_float4(v[0], v[1], v[2], v[3]);
            *reinterpret_cast<float4*>(cp + 4) = make_float4(v[4], v[5], v[6], v[7]);
        }
    }
}

// ---------------------------------------------------------------------------
// LIF0: per (n0, b) scan over t.  cur0T[n0][t*256+b] -> s0T[n0][t*256+b].
// ---------------------------------------------------------------------------
__global__ void lif0_kernel() {
    const int n0 = blockIdx.x;                 // 0..2047
    const int b  = threadIdx.x;                // 0..255
    const size_t base = (size_t)n0 * M0 + b;
    float m = 0.0f;
    #pragma unroll
    for (int t = 0; t < T_STEPS; ++t) {
        float s;
        lif_update(m, g_cur0T[base + t * BATCH], m, s);
        g_s0T[base + t * BATCH] = s;
    }
}

// ---------------------------------------------------------------------------
// LIF1: per (k-group of 4, b) scan over t; writes s1 row-major as float4.
// ---------------------------------------------------------------------------
__global__ void lif1_kernel() {
    const int kg = blockIdx.x;                 // 0..511  (k = kg*4 .. +3)
    const int b  = threadIdx.x;                // 0..255
    float m[4] = {0.f, 0.f, 0.f, 0.f};
    #pragma unroll 1
    for (int t = 0; t < T_STEPS; ++t) {
        const size_t moff = (size_t)t * BATCH + b;
        float s[4];
        #pragma unroll
        for (int j = 0; j < 4; j++) {
            float cur = g_cur1T[(size_t)(kg * 4 + j) * M0 + moff];
            lif_update(m[j], cur, m[j], s[j]);
        }
        *reinterpret_cast<float4*>(
            g_s1RM + ((size_t)t * BATCH + b) * F2 + kg * 4) =
            make_float4(s[0], s[1], s[2], s[3]);
    }
}

// ---------------------------------------------------------------------------
// SPARSE layer-2: task = (row m, half of 1024 cols). One warp per task.
// Chain: ascending k, skip zeros, add.rn.f32x2 of W2T rows (== dense chain).
// Writes cur2RM[m][n] = __fadd_rn(acc, bias[n]).
// ---------------------------------------------------------------------------
__global__ __launch_bounds__(128)
void sparse_l2_kernel(const float* __restrict__ b2) {
    const int warp = threadIdx.x >> 5, lane = threadIdx.x & 31;
    const int task = blockIdx.x * 4 + warp;    // 0 .. 12799
    const int m    = task >> 1;                // row (t*256+b)
    const int n0   = (task & 1) * 512;

    const float* s1b = g_s1RM + (size_t)m * F2;

    unsigned long long acc[4][2];
    #pragma unroll
    for (int c = 0; c < 4; c++) { acc[c][0] = 0ULL; acc[c][1] = 0ULL; }

    for (int base = 0; base < F2; base += 128) {
        const float4 sv = *reinterpret_cast<const float4*>(s1b + base + lane * 4);
        unsigned bl0 = __ballot_sync(0xffffffffu, sv.x != 0.0f);
        unsigned bl1 = __ballot_sync(0xffffffffu, sv.y != 0.0f);
        unsigned bl2 = __ballot_sync(0xffffffffu, sv.z != 0.0f);
        unsigned bl3 = __ballot_sync(0xffffffffu, sv.w != 0.0f);
        unsigned any = bl0 | bl1 | bl2 | bl3;
        while (any) {
            const int L = __ffs(any) - 1;
            any &= any - 1;
            const int kb = base + L * 4;
            #pragma unroll
            for (int j = 0; j < 4; j++) {
                const unsigned blj = (j == 0) ? bl0 : (j == 1) ? bl1
                                   : (j == 2) ? bl2 : bl3;
                if ((blj >> L) & 1u) {
                    const float* wr = g_wt2 + (size_t)(kb + j) * F3 + n0;
                    #pragma unroll
                    for (int c = 0; c < 4; c++) {
                        float4 w = *reinterpret_cast<const float4*>(
                            wr + c * 128 + lane * 4);
                        ADD2(acc[c][0], pk2(w.x, w.y));
                        ADD2(acc[c][1], pk2(w.z, w.w));
                    }
                }
            }
        }
    }

    float* crow = g_cur2RM + (size_t)m * F3;
    #pragma unroll
    for (int c = 0; c < 4; c++) {
        const int n = n0 + c * 128 + lane * 4;
        float a0, a1, a2, a3;
        upk2(a0, a1, acc[c][0]);
        upk2(a2, a3, acc[c][1]);
        float4 bv = *reinterpret_cast<const float4*>(b2 + n);
        *reinterpret_cast<float4*>(crow + n) =
            make_float4(__fadd_rn(a0, bv.x), __fadd_rn(a1, bv.y),
                        __fadd_rn(a2, bv.z), __fadd_rn(a3, bv.w));
    }
}

// ---------------------------------------------------------------------------
// LIF2: per (b, n) scan over t -> output spikes + final membrane.
// ---------------------------------------------------------------------------
__global__ void lif2_kernel(float* __restrict__ out, int write_mem) {
    const int id = blockIdx.x * blockDim.x + threadIdx.x;   // 0 .. 256*1024-1
    const int b = id >> 10, n = id & 1023;
    float m = 0.0f;
    #pragma unroll 1
    for (int t = 0; t < T_STEPS; ++t) {
        const size_t idx = ((size_t)t * BATCH + b) * F3 + n;
        float s;
        lif_update(m, g_cur2RM[idx], m, s);
        out[idx] = s;
    }
    if (write_mem)
        out[(size_t)T_STEPS * BATCH * F3 + (size_t)b * F3 + n] = m;
}

// ---------------------------------------------------------------------------
extern "C" void kernel_launch(void* const* d_in, const int* in_sizes, int n_in,
                              void* d_out, int out_size)
{
    (void)in_sizes; (void)n_in;
    const float* x  = (const float*)d_in[0];
    const float* w0 = (const float*)d_in[1];
    const float* b0 = (const float*)d_in[2];
    const float* w1 = (const float*)d_in[3];
    const float* b1 = (const float*)d_in[4];
    const float* w2 = (const float*)d_in[5];
    const float* b2 = (const float*)d_in[6];
    float* out = (float*)d_out;

    float *wt0, *wt1, *wt2, *xT, *cur0T, *s0T, *cur1T;
    cudaGetSymbolAddress((void**)&wt0, g_wt0);
    cudaGetSymbolAddress((void**)&wt1, g_wt1);
    cudaGetSymbolAddress((void**)&wt2, g_wt2);
    cudaGetSymbolAddress((void**)&xT,  g_xT);
    cudaGetSymbolAddress((void**)&cur0T, g_cur0T);
    cudaGetSymbolAddress((void**)&s0T,   g_s0T);
    cudaGetSymbolAddress((void**)&cur1T, g_cur1T);

    // prep: transposes (weights + x)
    {
        dim3 blk(32, 8);
        transpose_kernel<<<dim3(F0 / 32, F1 / 32), blk>>>(w0, wt0, F1, F0);
        transpose_kernel<<<dim3(F1 / 32, F2 / 32), blk>>>(w1, wt1, F2, F1);
        transpose_kernel<<<dim3(F2 / 32, F3 / 32), blk>>>(w2, wt2, F3, F2);
        transpose_kernel<<<dim3(F0 / 32, M0 / 32), blk>>>(x, xT, M0, F0);
    }

    // Layer 0: one GEMM over all timesteps, then elementwise LIF scan.
    gemm_big<<<dim3(F1 / 128, M0 / 64), 128>>>(xT, wt0, b0, cur0T, F0, F1);
    lif0_kernel<<<F1, BATCH>>>();

    // Layer 1: one GEMM (26.8 G-FMA), then LIF scan -> s1 row-major.
    gemm_big<<<dim3(F2 / 128, M0 / 64), 128>>>(s0T, wt1, b1, cur1T, F1, F2);
    lif1_kernel<<<F2 / 4, BATCH>>>();

    // Layer 2: sparse (spikes are 0/1), then LIF scan -> output.
    sparse_l2_kernel<<<(M0 * 2) / 4, 128>>>(b2);

    const long long mem_off = (long long)T_STEPS * BATCH * F3;
    const int write_mem =
        ((long long)out_size >= mem_off + (long long)BATCH * F3) ? 1 : 0;
    lif2_kernel<<<(BATCH * F3) / 256, 256>>>(out, write_mem);
}